// round 13
// baseline (speedup 1.0000x reference)
#include <cuda_runtime.h>
#include <math.h>
#include <stdint.h>

// SelfModifyingTitans — fp32 SIMT baseline.
// B=8, T=4096, D=256, CHUNK=64, 64 chunks processed sequentially; 8 batches in parallel.

#define NB 8
#define TSEQ 4096
#define DD 256
#define CH 64
#define NCHUNK 64
#define SMS 68   // padded smem row stride (64+4)

// ---- persistent per-batch state (re-initialized every launch) ----
__device__ __align__(128) float g_W1[NB][4][DD*DD];   // k,v,q,mem
__device__ __align__(128) float g_W2[NB][6][DD*DD];   // k,v,q,mem,eta,alpha
__device__ __align__(128) float g_u [NB][2][DD];      // eta_w1, alpha_w1
__device__ __align__(128) float g_s [NB][2][DD];      // eta_wskip, alpha_wskip
// ---- per-chunk scratch ----
__device__ __align__(128) float g_H  [NB][5][CH*DD];  // gelu(x@W2^T) for k,v,q,eta,alpha
__device__ __align__(128) float g_F  [NB][3][CH*DD];  // k,v,q (k,q normalized in place)
__device__ __align__(128) float g_Ho [NB][CH*DD];     // gelu(q@W2_mem^T)
__device__ __align__(128) float g_Zu [NB][6][CH*DD];  // raw z of update fwd (input k)
__device__ __align__(128) float g_Hu [NB][6][CH*DD];  // gelu(Zu)
__device__ __align__(128) float g_G  [NB][4][CH*DD];  // 2*(F - v) for D-mems
__device__ __align__(128) float g_Pre[NB][6][CH*DD];  // (G@W1)*dgelu(Zu), eta NOT applied
__device__ __align__(128) float g_eta[NB][CH];
__device__ __align__(128) float g_abar[NB];

__device__ __forceinline__ float gelu_f(float z){
    return 0.5f*z*(1.0f+erff(z*0.7071067811865475f));
}
__device__ __forceinline__ float dgelu_f(float z){
    float cdf = 0.5f*(1.0f+erff(z*0.7071067811865475f));
    float pdf = expf(-0.5f*z*z)*0.3989422804014327f;
    return cdf + z*pdf;
}

// ---- shared 64x64 tile GEMM core: C[x,y] = sum_k A'[k][x] * B'[k][y] ----
// aT=true : A stored [X][K] row-major (ld=lda)   -> A'[k][x]=A[x][k]
// aT=false: A stored [K][X] row-major            -> A'[k][x]=A[k][x], optional per-k scale
__device__ __forceinline__ void gemm_tile(
    const float* __restrict__ A, int lda, bool aT, const float* __restrict__ aks,
    const float* __restrict__ B, int ldb, bool bT,
    int x0, int y0, int K, float acc[4][4], float* As, float* Bs)
{
    const int tid = threadIdx.x;
    const int tr = tid>>4, tc = tid&15;
    for (int k0=0;k0<K;k0+=16){
        int idx = tid*4;
        if (aT){
            int xx = idx>>4, kk = idx&15;
            float4 v = *reinterpret_cast<const float4*>(A + (size_t)(x0+xx)*lda + (k0+kk));
            As[(kk+0)*SMS+xx]=v.x; As[(kk+1)*SMS+xx]=v.y;
            As[(kk+2)*SMS+xx]=v.z; As[(kk+3)*SMS+xx]=v.w;
        } else {
            int kk = idx>>6, xx = idx&63;
            float4 v = *reinterpret_cast<const float4*>(A + (size_t)(k0+kk)*lda + (x0+xx));
            if (aks){ float sc = aks[k0+kk]; v.x*=sc; v.y*=sc; v.z*=sc; v.w*=sc; }
            *reinterpret_cast<float4*>(&As[kk*SMS+xx]) = v;
        }
        if (bT){
            int xx = idx>>4, kk = idx&15;
            float4 v = *reinterpret_cast<const float4*>(B + (size_t)(y0+xx)*ldb + (k0+kk));
            Bs[(kk+0)*SMS+xx]=v.x; Bs[(kk+1)*SMS+xx]=v.y;
            Bs[(kk+2)*SMS+xx]=v.z; Bs[(kk+3)*SMS+xx]=v.w;
        } else {
            int kk = idx>>6, xx = idx&63;
            float4 v = *reinterpret_cast<const float4*>(B + (size_t)(k0+kk)*ldb + (y0+xx));
            *reinterpret_cast<float4*>(&Bs[kk*SMS+xx]) = v;
        }
        __syncthreads();
        #pragma unroll
        for (int k=0;k<16;k++){
            float a[4], b2[4];
            #pragma unroll
            for (int i=0;i<4;i++) a[i]=As[k*SMS+tr*4+i];
            #pragma unroll
            for (int j=0;j<4;j++) b2[j]=Bs[k*SMS+tc*4+j];
            #pragma unroll
            for (int i=0;i<4;i++)
                #pragma unroll
                for (int j=0;j<4;j++)
                    acc[i][j] = fmaf(a[i], b2[j], acc[i][j]);
        }
        __syncthreads();
    }
}

// ---- init: broadcast input weights into per-batch mutable state ----
__global__ void __launch_bounds__(256) k_init(
    const float* __restrict__ kw1,const float* __restrict__ kw2,
    const float* __restrict__ vw1,const float* __restrict__ vw2,
    const float* __restrict__ qw1,const float* __restrict__ qw2,
    const float* __restrict__ ew1,const float* __restrict__ ew2,const float* __restrict__ esk,
    const float* __restrict__ aw1,const float* __restrict__ aw2,const float* __restrict__ ask,
    const float* __restrict__ mw1,const float* __restrict__ mw2)
{
    int b = blockIdx.y, w = blockIdx.x;
    if (w < 10){
        const float* src; float* dst;
        switch(w){
            case 0: src=kw1; dst=g_W1[b][0]; break;
            case 1: src=vw1; dst=g_W1[b][1]; break;
            case 2: src=qw1; dst=g_W1[b][2]; break;
            case 3: src=mw1; dst=g_W1[b][3]; break;
            case 4: src=kw2; dst=g_W2[b][0]; break;
            case 5: src=vw2; dst=g_W2[b][1]; break;
            case 6: src=qw2; dst=g_W2[b][2]; break;
            case 7: src=mw2; dst=g_W2[b][3]; break;
            case 8: src=ew2; dst=g_W2[b][4]; break;
            default: src=aw2; dst=g_W2[b][5]; break;
        }
        for (int i=threadIdx.x; i<DD*DD; i+=256) dst[i]=src[i];
    } else {
        int i = threadIdx.x;
        g_u[b][0][i]=ew1[i]; g_u[b][1][i]=aw1[i];
        g_s[b][0][i]=esk[i]; g_s[b][1][i]=ask[i];
    }
}

// ---- K1: H_m = gelu(x @ W2_m^T), m in {k,v,q,eta,alpha} ----
__global__ void __launch_bounds__(256) k_fwdH(const float* __restrict__ x, int c){
    __shared__ __align__(16) float As[16*SMS], Bs[16*SMS];
    int b=blockIdx.z, m=blockIdx.y, nt=blockIdx.x;
    const int wmap[5]={0,1,2,4,5};
    const float* xc = x + ((size_t)b*TSEQ + (size_t)c*CH)*DD;
    float acc[4][4]={};
    gemm_tile(xc,DD,true,nullptr, g_W2[b][wmap[m]],DD,true, 0, nt*64, DD, acc, As, Bs);
    int tr=threadIdx.x>>4, tc=threadIdx.x&15;
    float* Hout = g_H[b][m];
    #pragma unroll
    for (int i=0;i<4;i++){
        int row=tr*4+i, col=nt*64+tc*4;
        float4 v; v.x=gelu_f(acc[i][0]); v.y=gelu_f(acc[i][1]);
        v.z=gelu_f(acc[i][2]); v.w=gelu_f(acc[i][3]);
        *reinterpret_cast<float4*>(&Hout[row*DD+col]) = v;
    }
}

// ---- K2: F_m = x + H_m @ W1_m^T, m in {k,v,q} ----
__global__ void __launch_bounds__(256) k_fwdF(const float* __restrict__ x, int c){
    __shared__ __align__(16) float As[16*SMS], Bs[16*SMS];
    int b=blockIdx.z, m=blockIdx.y, nt=blockIdx.x;
    const float* xc = x + ((size_t)b*TSEQ + (size_t)c*CH)*DD;
    float acc[4][4]={};
    gemm_tile(g_H[b][m],DD,true,nullptr, g_W1[b][m],DD,true, 0, nt*64, DD, acc, As, Bs);
    int tr=threadIdx.x>>4, tc=threadIdx.x&15;
    float* Fo = g_F[b][m];
    #pragma unroll
    for (int i=0;i<4;i++){
        int row=tr*4+i, col=nt*64+tc*4;
        float4 x4 = *reinterpret_cast<const float4*>(&xc[row*DD+col]);
        float4 v; v.x=acc[i][0]+x4.x; v.y=acc[i][1]+x4.y;
        v.z=acc[i][2]+x4.z; v.w=acc[i][3]+x4.w;
        *reinterpret_cast<float4*>(&Fo[row*DD+col]) = v;
    }
}

// ---- K3: l2norm(k), l2norm(q), eta, alpha, abar ----
__global__ void __launch_bounds__(256) k_small(const float* __restrict__ x, int c){
    __shared__ float s_alpha[CH], s_rk[CH], s_rq[CH];
    int b = blockIdx.x;
    const float* xc = x + ((size_t)b*TSEQ + (size_t)c*CH)*DD;
    int warp=threadIdx.x>>5, lane=threadIdx.x&31;
    for (int t=warp; t<CH; t+=8){
        float nk=0.f, nq=0.f, fe=0.f, fa=0.f;
        for (int i=lane;i<DD;i+=32){
            float vk=g_F[b][0][t*DD+i]; nk += vk*vk;
            float vq=g_F[b][2][t*DD+i]; nq += vq*vq;
            float xv=xc[t*DD+i];
            fe += xv*g_s[b][0][i] + g_H[b][3][t*DD+i]*g_u[b][0][i];
            fa += xv*g_s[b][1][i] + g_H[b][4][t*DD+i]*g_u[b][1][i];
        }
        #pragma unroll
        for (int off=16;off;off>>=1){
            nk += __shfl_down_sync(0xffffffffu,nk,off);
            nq += __shfl_down_sync(0xffffffffu,nq,off);
            fe += __shfl_down_sync(0xffffffffu,fe,off);
            fa += __shfl_down_sync(0xffffffffu,fa,off);
        }
        if (lane==0){
            s_rk[t] = 1.0f/fmaxf(sqrtf(nk),1e-6f);
            s_rq[t] = 1.0f/fmaxf(sqrtf(nq),1e-6f);
            float sp = (fe>20.0f)? fe : log1pf(expf(fe));
            g_eta[b][t] = sp*0.001f;
            s_alpha[t] = 1.0f/(1.0f+expf(-fa));
        }
    }
    __syncthreads();
    for (int idx=threadIdx.x; idx<CH*DD; idx+=256){
        int t = idx>>8;
        g_F[b][0][idx] *= s_rk[t];
        g_F[b][2][idx] *= s_rq[t];
    }
    if (threadIdx.x==0){
        float p=1.f;
        #pragma unroll
        for (int t=0;t<CH;t++) p*=s_alpha[t];
        g_abar[b]=p;
    }
}

// ---- K4: Ho = gelu(q @ W2_mem^T)  +  Zu_m = k @ W2_m^T (all 6) ----
__global__ void __launch_bounds__(256) k_A(int c){
    __shared__ __align__(16) float As[16*SMS], Bs[16*SMS];
    int b=blockIdx.y, t=blockIdx.x;
    int tr=threadIdx.x>>4, tc=threadIdx.x&15;
    float acc[4][4]={};
    if (t<4){
        gemm_tile(g_F[b][2],DD,true,nullptr, g_W2[b][3],DD,true, 0, t*64, DD, acc, As, Bs);
        float* Ho = g_Ho[b];
        #pragma unroll
        for (int i=0;i<4;i++){
            int row=tr*4+i, col=t*64+tc*4;
            float4 v; v.x=gelu_f(acc[i][0]); v.y=gelu_f(acc[i][1]);
            v.z=gelu_f(acc[i][2]); v.w=gelu_f(acc[i][3]);
            *reinterpret_cast<float4*>(&Ho[row*DD+col]) = v;
        }
    } else {
        int tt=t-4, m=tt>>2, nt=tt&3;
        gemm_tile(g_F[b][0],DD,true,nullptr, g_W2[b][m],DD,true, 0, nt*64, DD, acc, As, Bs);
        float* Zu=g_Zu[b][m]; float* Hu=g_Hu[b][m];
        #pragma unroll
        for (int i=0;i<4;i++){
            int row=tr*4+i, col=nt*64+tc*4;
            float4 z; z.x=acc[i][0]; z.y=acc[i][1]; z.z=acc[i][2]; z.w=acc[i][3];
            *reinterpret_cast<float4*>(&Zu[row*DD+col]) = z;
            float4 h; h.x=gelu_f(z.x); h.y=gelu_f(z.y); h.z=gelu_f(z.z); h.w=gelu_f(z.w);
            *reinterpret_cast<float4*>(&Hu[row*DD+col]) = h;
        }
    }
}

// ---- K5: O out  +  G = 2*(k + Hu@W1^T - v) (D-mems)  +  eta/alpha scalar-mem update ----
__global__ void __launch_bounds__(256) k_B(float* __restrict__ out, int c){
    __shared__ __align__(16) float As[16*SMS], Bs[16*SMS];
    __shared__ float sgv[CH];
    int b=blockIdx.y, t=blockIdx.x;
    int tr=threadIdx.x>>4, tc=threadIdx.x&15;
    if (t<4){
        float acc[4][4]={};
        gemm_tile(g_Ho[b],DD,true,nullptr, g_W1[b][3],DD,true, 0, t*64, DD, acc, As, Bs);
        const float* Q=g_F[b][2];
        #pragma unroll
        for (int i=0;i<4;i++){
            int row=tr*4+i, col=t*64+tc*4;
            float4 q4 = *reinterpret_cast<const float4*>(&Q[row*DD+col]);
            float4 v; v.x=acc[i][0]+q4.x; v.y=acc[i][1]+q4.y;
            v.z=acc[i][2]+q4.z; v.w=acc[i][3]+q4.w;
            *reinterpret_cast<float4*>(out + ((size_t)b*TSEQ + (size_t)c*CH + row)*DD + col) = v;
        }
    } else if (t<20){
        int tt=t-4, m=tt>>2, nt=tt&3;
        float acc[4][4]={};
        gemm_tile(g_Hu[b][m],DD,true,nullptr, g_W1[b][m],DD,true, 0, nt*64, DD, acc, As, Bs);
        const float* K=g_F[b][0]; const float* V=g_F[b][1];
        float* Gm = g_G[b][m];
        #pragma unroll
        for (int i=0;i<4;i++){
            int row=tr*4+i, col=nt*64+tc*4;
            float4 k4 = *reinterpret_cast<const float4*>(&K[row*DD+col]);
            float4 v4 = *reinterpret_cast<const float4*>(&V[row*DD+col]);
            float4 g4;
            g4.x = 2.0f*(k4.x+acc[i][0]-v4.x);
            g4.y = 2.0f*(k4.y+acc[i][1]-v4.y);
            g4.z = 2.0f*(k4.z+acc[i][2]-v4.z);
            g4.w = 2.0f*(k4.w+acc[i][3]-v4.w);
            *reinterpret_cast<float4*>(&Gm[row*DD+col]) = g4;
        }
    } else {
        // scalar memories (eta: j=0, alpha: j=1)
        int j=t-20, widx=4+j;
        const float* Zu=g_Zu[b][widx]; const float* Hu=g_Hu[b][widx];
        float* u=g_u[b][j]; float* sk=g_s[b][j];
        const float* K=g_F[b][0]; const float* V=g_F[b][1];
        int warp=threadIdx.x>>5, lane=threadIdx.x&31;
        for (int tok=warp; tok<CH; tok+=8){
            float f=0.f, vs=0.f;
            for (int i=lane;i<DD;i+=32){
                f  += K[tok*DD+i]*sk[i] + Hu[tok*DD+i]*u[i];
                vs += V[tok*DD+i];
            }
            #pragma unroll
            for (int off=16;off;off>>=1){
                f  += __shfl_down_sync(0xffffffffu,f,off);
                vs += __shfl_down_sync(0xffffffffu,vs,off);
            }
            if (lane==0) sgv[tok] = 2.0f*(256.0f*f - vs);   // 2*sum_d(f - v_d)
        }
        __syncthreads();
        int h=threadIdx.x;
        float uh=u[h], gu=0.f, gs=0.f;
        float* Pm = g_Pre[b][widx];
        for (int tok=0;tok<CH;tok++){
            float z  = Zu[tok*DD+h];
            float gt = sgv[tok];
            Pm[tok*DD+h] = gt*uh*dgelu_f(z);           // Pre (old u), eta applied later
            float w = g_eta[b][tok]*gt;
            gu += w*Hu[tok*DD+h];
            gs += w*K[tok*DD+h];
        }
        float ab = g_abar[b];
        u[h]  = ab*uh   - gu;
        sk[h] = ab*sk[h] - gs;
    }
}

// ---- K6: Pre = (G @ W1) * dgelu(Zu), D-mems ----
__global__ void __launch_bounds__(256) k_C(int c){
    __shared__ __align__(16) float As[16*SMS], Bs[16*SMS];
    int b=blockIdx.z, m=blockIdx.y, nt=blockIdx.x;
    float acc[4][4]={};
    gemm_tile(g_G[b][m],DD,true,nullptr, g_W1[b][m],DD,false, 0, nt*64, DD, acc, As, Bs);
    int tr=threadIdx.x>>4, tc=threadIdx.x&15;
    const float* Zu=g_Zu[b][m]; float* Pm=g_Pre[b][m];
    #pragma unroll
    for (int i=0;i<4;i++){
        int row=tr*4+i, col=nt*64+tc*4;
        float4 z4 = *reinterpret_cast<const float4*>(&Zu[row*DD+col]);
        float4 v;
        v.x = acc[i][0]*dgelu_f(z4.x);
        v.y = acc[i][1]*dgelu_f(z4.y);
        v.z = acc[i][2]*dgelu_f(z4.z);
        v.w = acc[i][3]*dgelu_f(z4.w);
        *reinterpret_cast<float4*>(&Pm[row*DD+col]) = v;
    }
}

// ---- K7: W1 <- abar*W1 - (etaG)^T Hu ; W2 <- abar*W2 - (etaPre)^T k ----
__global__ void __launch_bounds__(256) k_D(int c){
    __shared__ __align__(16) float As[16*SMS], Bs[16*SMS];
    int b=blockIdx.y, t=blockIdx.x;
    int tr=threadIdx.x>>4, tc=threadIdx.x&15;
    float ab=g_abar[b];
    float acc[4][4]={};
    if (t<64){
        int m=t>>4, tile=t&15;
        int o0=(tile>>2)*64, h0=(tile&3)*64;
        gemm_tile(g_G[b][m],DD,false,g_eta[b], g_Hu[b][m],DD,false, o0, h0, CH, acc, As, Bs);
        float* W=g_W1[b][m];
        #pragma unroll
        for (int i=0;i<4;i++){
            int row=o0+tr*4+i, col=h0+tc*4;
            float4 w4 = *reinterpret_cast<const float4*>(&W[row*DD+col]);
            w4.x=ab*w4.x-acc[i][0]; w4.y=ab*w4.y-acc[i][1];
            w4.z=ab*w4.z-acc[i][2]; w4.w=ab*w4.w-acc[i][3];
            *reinterpret_cast<float4*>(&W[row*DD+col]) = w4;
        }
    } else {
        int tt=t-64, m=tt>>4, tile=tt&15;
        int h0=(tile>>2)*64, i0=(tile&3)*64;
        gemm_tile(g_Pre[b][m],DD,false,g_eta[b], g_F[b][0],DD,false, h0, i0, CH, acc, As, Bs);
        float* W=g_W2[b][m];
        #pragma unroll
        for (int i=0;i<4;i++){
            int row=h0+tr*4+i, col=i0+tc*4;
            float4 w4 = *reinterpret_cast<const float4*>(&W[row*DD+col]);
            w4.x=ab*w4.x-acc[i][0]; w4.y=ab*w4.y-acc[i][1];
            w4.z=ab*w4.z-acc[i][2]; w4.w=ab*w4.w-acc[i][3];
            *reinterpret_cast<float4*>(&W[row*DD+col]) = w4;
        }
    }
}

extern "C" void kernel_launch(void* const* d_in, const int* in_sizes, int n_in,
                              void* d_out, int out_size)
{
    const float* x    = (const float*)d_in[0];
    const float* kw1  = (const float*)d_in[1];
    const float* kw2  = (const float*)d_in[2];
    const float* vw1  = (const float*)d_in[3];
    const float* vw2  = (const float*)d_in[4];
    const float* qw1  = (const float*)d_in[5];
    const float* qw2  = (const float*)d_in[6];
    const float* ew1  = (const float*)d_in[7];
    const float* ew2  = (const float*)d_in[8];
    const float* esk  = (const float*)d_in[9];
    const float* aw1  = (const float*)d_in[10];
    const float* aw2  = (const float*)d_in[11];
    const float* ask  = (const float*)d_in[12];
    const float* mw1  = (const float*)d_in[13];
    const float* mw2  = (const float*)d_in[14];
    float* out = (float*)d_out;

    k_init<<<dim3(11,NB), 256>>>(kw1,kw2,vw1,vw2,qw1,qw2,ew1,ew2,esk,aw1,aw2,ask,mw1,mw2);

    for (int c=0; c<NCHUNK; c++){
        k_fwdH <<<dim3(4,5,NB), 256>>>(x, c);
        k_fwdF <<<dim3(4,3,NB), 256>>>(x, c);
        k_small<<<NB,          256>>>(x, c);
        k_A    <<<dim3(28,NB), 256>>>(c);
        k_B    <<<dim3(22,NB), 256>>>(out, c);
        k_C    <<<dim3(4,4,NB),256>>>(c);
        k_D    <<<dim3(160,NB),256>>>(c);
    }
}

// round 17
// speedup vs baseline: 1.0135x; 1.0135x over previous
#include <cuda_runtime.h>
#include <math.h>
#include <stdint.h>

// SelfModifyingTitans — fp32 SIMT baseline.
// B=8, T=4096, D=256, CHUNK=64, 64 chunks processed sequentially; 8 batches in parallel.

#define NB 8
#define TSEQ 4096
#define DD 256
#define CH 64
#define NCHUNK 64
#define SMS 68   // padded smem row stride (64+4)

// ---- persistent per-batch state (re-initialized every launch) ----
__device__ __align__(128) float g_W1[NB][4][DD*DD];   // k,v,q,mem
__device__ __align__(128) float g_W2[NB][6][DD*DD];   // k,v,q,mem,eta,alpha
__device__ __align__(128) float g_u [NB][2][DD];      // eta_w1, alpha_w1
__device__ __align__(128) float g_s [NB][2][DD];      // eta_wskip, alpha_wskip
// ---- per-chunk scratch ----
__device__ __align__(128) float g_H  [NB][5][CH*DD];  // gelu(x@W2^T) for k,v,q,eta,alpha
__device__ __align__(128) float g_F  [NB][3][CH*DD];  // k,v,q (k,q normalized in place)
__device__ __align__(128) float g_Ho [NB][CH*DD];     // gelu(q@W2_mem^T)
__device__ __align__(128) float g_Zu [NB][6][CH*DD];  // raw z of update fwd (input k)
__device__ __align__(128) float g_Hu [NB][6][CH*DD];  // gelu(Zu)
__device__ __align__(128) float g_G  [NB][4][CH*DD];  // 2*(F - v) for D-mems
__device__ __align__(128) float g_Pre[NB][6][CH*DD];  // (G@W1)*dgelu(Zu), eta NOT applied
__device__ __align__(128) float g_eta[NB][CH];
__device__ __align__(128) float g_abar[NB];

__device__ __forceinline__ float gelu_f(float z){
    return 0.5f*z*(1.0f+erff(z*0.7071067811865475f));
}
__device__ __forceinline__ float dgelu_f(float z){
    float cdf = 0.5f*(1.0f+erff(z*0.7071067811865475f));
    float pdf = expf(-0.5f*z*z)*0.3989422804014327f;
    return cdf + z*pdf;
}

// ---- shared 64x64 tile GEMM core: C[x,y] = sum_k A'[k][x] * B'[k][y] ----
// aT=true : A stored [X][K] row-major (ld=lda)   -> A'[k][x]=A[x][k]
// aT=false: A stored [K][X] row-major            -> A'[k][x]=A[k][x], optional per-k scale
__device__ __forceinline__ void gemm_tile(
    const float* __restrict__ A, int lda, bool aT, const float* __restrict__ aks,
    const float* __restrict__ B, int ldb, bool bT,
    int x0, int y0, int K, float acc[4][4], float* As, float* Bs)
{
    const int tid = threadIdx.x;
    const int tr = tid>>4, tc = tid&15;
    for (int k0=0;k0<K;k0+=16){
        int idx = tid*4;
        if (aT){
            int xx = idx>>4, kk = idx&15;
            float4 v = *reinterpret_cast<const float4*>(A + (size_t)(x0+xx)*lda + (k0+kk));
            As[(kk+0)*SMS+xx]=v.x; As[(kk+1)*SMS+xx]=v.y;
            As[(kk+2)*SMS+xx]=v.z; As[(kk+3)*SMS+xx]=v.w;
        } else {
            int kk = idx>>6, xx = idx&63;
            float4 v = *reinterpret_cast<const float4*>(A + (size_t)(k0+kk)*lda + (x0+xx));
            if (aks){ float sc = aks[k0+kk]; v.x*=sc; v.y*=sc; v.z*=sc; v.w*=sc; }
            *reinterpret_cast<float4*>(&As[kk*SMS+xx]) = v;
        }
        if (bT){
            int xx = idx>>4, kk = idx&15;
            float4 v = *reinterpret_cast<const float4*>(B + (size_t)(y0+xx)*ldb + (k0+kk));
            Bs[(kk+0)*SMS+xx]=v.x; Bs[(kk+1)*SMS+xx]=v.y;
            Bs[(kk+2)*SMS+xx]=v.z; Bs[(kk+3)*SMS+xx]=v.w;
        } else {
            int kk = idx>>6, xx = idx&63;
            float4 v = *reinterpret_cast<const float4*>(B + (size_t)(k0+kk)*ldb + (y0+xx));
            *reinterpret_cast<float4*>(&Bs[kk*SMS+xx]) = v;
        }
        __syncthreads();
        #pragma unroll
        for (int k=0;k<16;k++){
            float a[4], b2[4];
            #pragma unroll
            for (int i=0;i<4;i++) a[i]=As[k*SMS+tr*4+i];
            #pragma unroll
            for (int j=0;j<4;j++) b2[j]=Bs[k*SMS+tc*4+j];
            #pragma unroll
            for (int i=0;i<4;i++)
                #pragma unroll
                for (int j=0;j<4;j++)
                    acc[i][j] = fmaf(a[i], b2[j], acc[i][j]);
        }
        __syncthreads();
    }
}

// ---- init: broadcast input weights into per-batch mutable state ----
__global__ void __launch_bounds__(256) k_init(
    const float* __restrict__ kw1,const float* __restrict__ kw2,
    const float* __restrict__ vw1,const float* __restrict__ vw2,
    const float* __restrict__ qw1,const float* __restrict__ qw2,
    const float* __restrict__ ew1,const float* __restrict__ ew2,const float* __restrict__ esk,
    const float* __restrict__ aw1,const float* __restrict__ aw2,const float* __restrict__ ask,
    const float* __restrict__ mw1,const float* __restrict__ mw2)
{
    int b = blockIdx.y, w = blockIdx.x;
    if (w < 10){
        const float* src; float* dst;
        switch(w){
            case 0: src=kw1; dst=g_W1[b][0]; break;
            case 1: src=vw1; dst=g_W1[b][1]; break;
            case 2: src=qw1; dst=g_W1[b][2]; break;
            case 3: src=mw1; dst=g_W1[b][3]; break;
            case 4: src=kw2; dst=g_W2[b][0]; break;
            case 5: src=vw2; dst=g_W2[b][1]; break;
            case 6: src=qw2; dst=g_W2[b][2]; break;
            case 7: src=mw2; dst=g_W2[b][3]; break;
            case 8: src=ew2; dst=g_W2[b][4]; break;
            default: src=aw2; dst=g_W2[b][5]; break;
        }
        for (int i=threadIdx.x; i<DD*DD; i+=256) dst[i]=src[i];
    } else {
        int i = threadIdx.x;
        g_u[b][0][i]=ew1[i]; g_u[b][1][i]=aw1[i];
        g_s[b][0][i]=esk[i]; g_s[b][1][i]=ask[i];
    }
}

// ---- K1: H_m = gelu(x @ W2_m^T), m in {k,v,q,eta,alpha} ----
__global__ void __launch_bounds__(256) k_fwdH(const float* __restrict__ x, int c){
    __shared__ __align__(16) float As[16*SMS], Bs[16*SMS];
    int b=blockIdx.z, m=blockIdx.y, nt=blockIdx.x;
    const int wmap[5]={0,1,2,4,5};
    const float* xc = x + ((size_t)b*TSEQ + (size_t)c*CH)*DD;
    float acc[4][4]={};
    gemm_tile(xc,DD,true,nullptr, g_W2[b][wmap[m]],DD,true, 0, nt*64, DD, acc, As, Bs);
    int tr=threadIdx.x>>4, tc=threadIdx.x&15;
    float* Hout = g_H[b][m];
    #pragma unroll
    for (int i=0;i<4;i++){
        int row=tr*4+i, col=nt*64+tc*4;
        float4 v; v.x=gelu_f(acc[i][0]); v.y=gelu_f(acc[i][1]);
        v.z=gelu_f(acc[i][2]); v.w=gelu_f(acc[i][3]);
        *reinterpret_cast<float4*>(&Hout[row*DD+col]) = v;
    }
}

// ---- K2: F_m = x + H_m @ W1_m^T, m in {k,v,q} ----
__global__ void __launch_bounds__(256) k_fwdF(const float* __restrict__ x, int c){
    __shared__ __align__(16) float As[16*SMS], Bs[16*SMS];
    int b=blockIdx.z, m=blockIdx.y, nt=blockIdx.x;
    const float* xc = x + ((size_t)b*TSEQ + (size_t)c*CH)*DD;
    float acc[4][4]={};
    gemm_tile(g_H[b][m],DD,true,nullptr, g_W1[b][m],DD,true, 0, nt*64, DD, acc, As, Bs);
    int tr=threadIdx.x>>4, tc=threadIdx.x&15;
    float* Fo = g_F[b][m];
    #pragma unroll
    for (int i=0;i<4;i++){
        int row=tr*4+i, col=nt*64+tc*4;
        float4 x4 = *reinterpret_cast<const float4*>(&xc[row*DD+col]);
        float4 v; v.x=acc[i][0]+x4.x; v.y=acc[i][1]+x4.y;
        v.z=acc[i][2]+x4.z; v.w=acc[i][3]+x4.w;
        *reinterpret_cast<float4*>(&Fo[row*DD+col]) = v;
    }
}

// ---- K3: l2norm(k), l2norm(q), eta, alpha, abar ----
__global__ void __launch_bounds__(256) k_small(const float* __restrict__ x, int c){
    __shared__ float s_alpha[CH], s_rk[CH], s_rq[CH];
    int b = blockIdx.x;
    const float* xc = x + ((size_t)b*TSEQ + (size_t)c*CH)*DD;
    int warp=threadIdx.x>>5, lane=threadIdx.x&31;
    for (int t=warp; t<CH; t+=8){
        float nk=0.f, nq=0.f, fe=0.f, fa=0.f;
        for (int i=lane;i<DD;i+=32){
            float vk=g_F[b][0][t*DD+i]; nk += vk*vk;
            float vq=g_F[b][2][t*DD+i]; nq += vq*vq;
            float xv=xc[t*DD+i];
            fe += xv*g_s[b][0][i] + g_H[b][3][t*DD+i]*g_u[b][0][i];
            fa += xv*g_s[b][1][i] + g_H[b][4][t*DD+i]*g_u[b][1][i];
        }
        #pragma unroll
        for (int off=16;off;off>>=1){
            nk += __shfl_down_sync(0xffffffffu,nk,off);
            nq += __shfl_down_sync(0xffffffffu,nq,off);
            fe += __shfl_down_sync(0xffffffffu,fe,off);
            fa += __shfl_down_sync(0xffffffffu,fa,off);
        }
        if (lane==0){
            s_rk[t] = 1.0f/fmaxf(sqrtf(nk),1e-6f);
            s_rq[t] = 1.0f/fmaxf(sqrtf(nq),1e-6f);
            float sp = (fe>20.0f)? fe : log1pf(expf(fe));
            g_eta[b][t] = sp*0.001f;
            s_alpha[t] = 1.0f/(1.0f+expf(-fa));
        }
    }
    __syncthreads();
    for (int idx=threadIdx.x; idx<CH*DD; idx+=256){
        int t = idx>>8;
        g_F[b][0][idx] *= s_rk[t];
        g_F[b][2][idx] *= s_rq[t];
    }
    if (threadIdx.x==0){
        float p=1.f;
        #pragma unroll
        for (int t=0;t<CH;t++) p*=s_alpha[t];
        g_abar[b]=p;
    }
}

// ---- K4: Ho = gelu(q @ W2_mem^T)  +  Zu_m = k @ W2_m^T (all 6) ----
__global__ void __launch_bounds__(256) k_A(int c){
    __shared__ __align__(16) float As[16*SMS], Bs[16*SMS];
    int b=blockIdx.y, t=blockIdx.x;
    int tr=threadIdx.x>>4, tc=threadIdx.x&15;
    float acc[4][4]={};
    if (t<4){
        gemm_tile(g_F[b][2],DD,true,nullptr, g_W2[b][3],DD,true, 0, t*64, DD, acc, As, Bs);
        float* Ho = g_Ho[b];
        #pragma unroll
        for (int i=0;i<4;i++){
            int row=tr*4+i, col=t*64+tc*4;
            float4 v; v.x=gelu_f(acc[i][0]); v.y=gelu_f(acc[i][1]);
            v.z=gelu_f(acc[i][2]); v.w=gelu_f(acc[i][3]);
            *reinterpret_cast<float4*>(&Ho[row*DD+col]) = v;
        }
    } else {
        int tt=t-4, m=tt>>2, nt=tt&3;
        gemm_tile(g_F[b][0],DD,true,nullptr, g_W2[b][m],DD,true, 0, nt*64, DD, acc, As, Bs);
        float* Zu=g_Zu[b][m]; float* Hu=g_Hu[b][m];
        #pragma unroll
        for (int i=0;i<4;i++){
            int row=tr*4+i, col=nt*64+tc*4;
            float4 z; z.x=acc[i][0]; z.y=acc[i][1]; z.z=acc[i][2]; z.w=acc[i][3];
            *reinterpret_cast<float4*>(&Zu[row*DD+col]) = z;
            float4 h; h.x=gelu_f(z.x); h.y=gelu_f(z.y); h.z=gelu_f(z.z); h.w=gelu_f(z.w);
            *reinterpret_cast<float4*>(&Hu[row*DD+col]) = h;
        }
    }
}

// ---- K5: O out  +  G = 2*(k + Hu@W1^T - v) (D-mems)  +  eta/alpha scalar-mem update ----
__global__ void __launch_bounds__(256) k_B(float* __restrict__ out, int c){
    __shared__ __align__(16) float As[16*SMS], Bs[16*SMS];
    __shared__ float sgv[CH];
    int b=blockIdx.y, t=blockIdx.x;
    int tr=threadIdx.x>>4, tc=threadIdx.x&15;
    if (t<4){
        float acc[4][4]={};
        gemm_tile(g_Ho[b],DD,true,nullptr, g_W1[b][3],DD,true, 0, t*64, DD, acc, As, Bs);
        const float* Q=g_F[b][2];
        #pragma unroll
        for (int i=0;i<4;i++){
            int row=tr*4+i, col=t*64+tc*4;
            float4 q4 = *reinterpret_cast<const float4*>(&Q[row*DD+col]);
            float4 v; v.x=acc[i][0]+q4.x; v.y=acc[i][1]+q4.y;
            v.z=acc[i][2]+q4.z; v.w=acc[i][3]+q4.w;
            *reinterpret_cast<float4*>(out + ((size_t)b*TSEQ + (size_t)c*CH + row)*DD + col) = v;
        }
    } else if (t<20){
        int tt=t-4, m=tt>>2, nt=tt&3;
        float acc[4][4]={};
        gemm_tile(g_Hu[b][m],DD,true,nullptr, g_W1[b][m],DD,true, 0, nt*64, DD, acc, As, Bs);
        const float* K=g_F[b][0]; const float* V=g_F[b][1];
        float* Gm = g_G[b][m];
        #pragma unroll
        for (int i=0;i<4;i++){
            int row=tr*4+i, col=nt*64+tc*4;
            float4 k4 = *reinterpret_cast<const float4*>(&K[row*DD+col]);
            float4 v4 = *reinterpret_cast<const float4*>(&V[row*DD+col]);
            float4 g4;
            g4.x = 2.0f*(k4.x+acc[i][0]-v4.x);
            g4.y = 2.0f*(k4.y+acc[i][1]-v4.y);
            g4.z = 2.0f*(k4.z+acc[i][2]-v4.z);
            g4.w = 2.0f*(k4.w+acc[i][3]-v4.w);
            *reinterpret_cast<float4*>(&Gm[row*DD+col]) = g4;
        }
    } else {
        // scalar memories (eta: j=0, alpha: j=1)
        int j=t-20, widx=4+j;
        const float* Zu=g_Zu[b][widx]; const float* Hu=g_Hu[b][widx];
        float* u=g_u[b][j]; float* sk=g_s[b][j];
        const float* K=g_F[b][0]; const float* V=g_F[b][1];
        int warp=threadIdx.x>>5, lane=threadIdx.x&31;
        for (int tok=warp; tok<CH; tok+=8){
            float f=0.f, vs=0.f;
            for (int i=lane;i<DD;i+=32){
                f  += K[tok*DD+i]*sk[i] + Hu[tok*DD+i]*u[i];
                vs += V[tok*DD+i];
            }
            #pragma unroll
            for (int off=16;off;off>>=1){
                f  += __shfl_down_sync(0xffffffffu,f,off);
                vs += __shfl_down_sync(0xffffffffu,vs,off);
            }
            if (lane==0) sgv[tok] = 2.0f*(256.0f*f - vs);   // 2*sum_d(f - v_d)
        }
        __syncthreads();
        int h=threadIdx.x;
        float uh=u[h], gu=0.f, gs=0.f;
        float* Pm = g_Pre[b][widx];
        for (int tok=0;tok<CH;tok++){
            float z  = Zu[tok*DD+h];
            float gt = sgv[tok];
            Pm[tok*DD+h] = gt*uh*dgelu_f(z);           // Pre (old u), eta applied later
            float w = g_eta[b][tok]*gt;
            gu += w*Hu[tok*DD+h];
            gs += w*K[tok*DD+h];
        }
        float ab = g_abar[b];
        u[h]  = ab*uh   - gu;
        sk[h] = ab*sk[h] - gs;
    }
}

// ---- K6: Pre = (G @ W1) * dgelu(Zu), D-mems ----
__global__ void __launch_bounds__(256) k_C(int c){
    __shared__ __align__(16) float As[16*SMS], Bs[16*SMS];
    int b=blockIdx.z, m=blockIdx.y, nt=blockIdx.x;
    float acc[4][4]={};
    gemm_tile(g_G[b][m],DD,true,nullptr, g_W1[b][m],DD,false, 0, nt*64, DD, acc, As, Bs);
    int tr=threadIdx.x>>4, tc=threadIdx.x&15;
    const float* Zu=g_Zu[b][m]; float* Pm=g_Pre[b][m];
    #pragma unroll
    for (int i=0;i<4;i++){
        int row=tr*4+i, col=nt*64+tc*4;
        float4 z4 = *reinterpret_cast<const float4*>(&Zu[row*DD+col]);
        float4 v;
        v.x = acc[i][0]*dgelu_f(z4.x);
        v.y = acc[i][1]*dgelu_f(z4.y);
        v.z = acc[i][2]*dgelu_f(z4.z);
        v.w = acc[i][3]*dgelu_f(z4.w);
        *reinterpret_cast<float4*>(&Pm[row*DD+col]) = v;
    }
}

// ---- K7: W1 <- abar*W1 - (etaG)^T Hu ; W2 <- abar*W2 - (etaPre)^T k ----
__global__ void __launch_bounds__(256) k_D(int c){
    __shared__ __align__(16) float As[16*SMS], Bs[16*SMS];
    int b=blockIdx.y, t=blockIdx.x;
    int tr=threadIdx.x>>4, tc=threadIdx.x&15;
    float ab=g_abar[b];
    float acc[4][4]={};
    if (t<64){
        int m=t>>4, tile=t&15;
        int o0=(tile>>2)*64, h0=(tile&3)*64;
        gemm_tile(g_G[b][m],DD,false,g_eta[b], g_Hu[b][m],DD,false, o0, h0, CH, acc, As, Bs);
        float* W=g_W1[b][m];
        #pragma unroll
        for (int i=0;i<4;i++){
            int row=o0+tr*4+i, col=h0+tc*4;
            float4 w4 = *reinterpret_cast<const float4*>(&W[row*DD+col]);
            w4.x=ab*w4.x-acc[i][0]; w4.y=ab*w4.y-acc[i][1];
            w4.z=ab*w4.z-acc[i][2]; w4.w=ab*w4.w-acc[i][3];
            *reinterpret_cast<float4*>(&W[row*DD+col]) = w4;
        }
    } else {
        int tt=t-64, m=tt>>4, tile=tt&15;
        int h0=(tile>>2)*64, i0=(tile&3)*64;
        gemm_tile(g_Pre[b][m],DD,false,g_eta[b], g_F[b][0],DD,false, h0, i0, CH, acc, As, Bs);
        float* W=g_W2[b][m];
        #pragma unroll
        for (int i=0;i<4;i++){
            int row=h0+tr*4+i, col=i0+tc*4;
            float4 w4 = *reinterpret_cast<const float4*>(&W[row*DD+col]);
            w4.x=ab*w4.x-acc[i][0]; w4.y=ab*w4.y-acc[i][1];
            w4.z=ab*w4.z-acc[i][2]; w4.w=ab*w4.w-acc[i][3];
            *reinterpret_cast<float4*>(&W[row*DD+col]) = w4;
        }
    }
}

extern "C" void kernel_launch(void* const* d_in, const int* in_sizes, int n_in,
                              void* d_out, int out_size)
{
    const float* x    = (const float*)d_in[0];
    const float* kw1  = (const float*)d_in[1];
    const float* kw2  = (const float*)d_in[2];
    const float* vw1  = (const float*)d_in[3];
    const float* vw2  = (const float*)d_in[4];
    const float* qw1  = (const float*)d_in[5];
    const float* qw2  = (const float*)d_in[6];
    const float* ew1  = (const float*)d_in[7];
    const float* ew2  = (const float*)d_in[8];
    const float* esk  = (const float*)d_in[9];
    const float* aw1  = (const float*)d_in[10];
    const float* aw2  = (const float*)d_in[11];
    const float* ask  = (const float*)d_in[12];
    const float* mw1  = (const float*)d_in[13];
    const float* mw2  = (const float*)d_in[14];
    float* out = (float*)d_out;

    k_init<<<dim3(11,NB), 256>>>(kw1,kw2,vw1,vw2,qw1,qw2,ew1,ew2,esk,aw1,aw2,ask,mw1,mw2);

    for (int c=0; c<NCHUNK; c++){
        k_fwdH <<<dim3(4,5,NB), 256>>>(x, c);
        k_fwdF <<<dim3(4,3,NB), 256>>>(x, c);
        k_small<<<NB,          256>>>(x, c);
        k_A    <<<dim3(28,NB), 256>>>(c);
        k_B    <<<dim3(22,NB), 256>>>(out, c);
        k_C    <<<dim3(4,4,NB),256>>>(c);
        k_D    <<<dim3(160,NB),256>>>(c);
    }
}